// round 3
// baseline (speedup 1.0000x reference)
#include <cuda_runtime.h>
#include <cuda_fp16.h>
#include <cstdint>
#include <cstddef>

#define N_OSC 4096
#define NB 128               // persistent blocks (one per SM, <=148)
#define FLAG_STRIDE 32       // one flag per 128B line
#define DT_C 0.01f
#define TWO_PI_F 6.283185307179586f
#define INV_TWO_PI_F 0.15915494309189535f

// ---------------- device scratch (static, no allocation) ----------------
__device__ __half g_W[(size_t)N_OSC * N_OSC];   // 32 MB effective coupling, fp16
__device__ float2 g_sc[2][N_OSC];               // double-buffered (sin, cos)
__device__ float  g_ext[4][N_OSC];              // tanh(x@enc_w+enc_b)
__device__ int    g_flags[NB * FLAG_STRIDE];    // per-block progress flags

__device__ __forceinline__ int padi(int i) { return i + (i >> 3); }

// ---------------- prep: zero flags, write bias into output ----------------
__global__ void prep_kernel(float* __restrict__ out, const float* __restrict__ rb) {
    int i = blockIdx.x * blockDim.x + threadIdx.x;
    if (i < NB) g_flags[i * FLAG_STRIDE] = 0;
    if (i < 4000) out[i] = rb[i % 1000];
}

// ---------------- W = sigmoid(adj_logits) * (1-eye) * coupling, fp16 ------
__global__ void build_w_kernel(const float* __restrict__ adj, const float* __restrict__ cpl) {
    size_t idx  = (size_t)blockIdx.x * blockDim.x + threadIdx.x;
    size_t base = idx * 4;
    float4 a = ((const float4*)adj)[idx];
    float4 k = ((const float4*)cpl)[idx];
    int row = (int)(base >> 12);
    int col = (int)(base & 4095);
    float w0 = k.x / (1.0f + expf(-a.x));
    float w1 = k.y / (1.0f + expf(-a.y));
    float w2 = k.z / (1.0f + expf(-a.z));
    float w3 = k.w / (1.0f + expf(-a.w));
    if (col     == row) w0 = 0.0f;
    if (col + 1 == row) w1 = 0.0f;
    if (col + 2 == row) w2 = 0.0f;
    if (col + 3 == row) w3 = 0.0f;
    __half2* o = (__half2*)(g_W + base);
    o[0] = __floats2half2_rn(w0, w1);
    o[1] = __floats2half2_rn(w2, w3);
}

// ---------------- ext = tanh(x @ enc_w + enc_b), [4, 4096] ----------------
__global__ void encoder_kernel(const float* __restrict__ x,
                               const float* __restrict__ enc_w,
                               const float* __restrict__ enc_b) {
    __shared__ float xs[4 * 2048];
    int tid = threadIdx.x;
    for (int i = tid; i < 8192; i += 256) xs[i] = x[i];
    __syncthreads();
    int n = blockIdx.x * 256 + tid;
    float a0 = 0.f, a1 = 0.f, a2 = 0.f, a3 = 0.f;
    for (int d = 0; d < 2048; d++) {
        float w = enc_w[(size_t)d * N_OSC + n];
        a0 += xs[d]        * w;
        a1 += xs[2048 + d] * w;
        a2 += xs[4096 + d] * w;
        a3 += xs[6144 + d] * w;
    }
    float b = enc_b[n];
    g_ext[0][n] = tanhf(a0 + b);
    g_ext[1][n] = tanhf(a1 + b);
    g_ext[2][n] = tanhf(a2 + b);
    g_ext[3][n] = tanhf(a3 + b);
}

// ---------------- persistent Kuramoto integrator + readout ----------------
__global__ void __launch_bounds__(256, 1)
kuramoto_kernel(const float* __restrict__ omega,
                const float* __restrict__ init_phases,
                const float* __restrict__ kstr,
                const float* __restrict__ readout_w,
                float* __restrict__ out) {
    __shared__ float s_sm[4608], c_sm[4608];          // padded sin/cos vectors
    __shared__ float redS[2][4][8], redC[2][4][8];    // [half][group][row]
    __shared__ float my_s[32], my_c[32], phi_sm[32], om_sm[32], ext_sm[32];
    __shared__ float sh_scale;

    const int tid  = threadIdx.x;
    const int bid  = blockIdx.x;
    const int lane = tid & 31;
    const int warp = tid >> 5;
    const int rowbase = bid * 32;

    // ---- init: phases, omega, initial sin/cos published to buffer 0 ----
    if (tid == 0) sh_scale = kstr[0] * (1.0f / (float)N_OSC);
    if (tid < 32) {
        float p = init_phases[rowbase + tid];
        phi_sm[tid] = p;
        om_sm[tid]  = omega[rowbase + tid];
        float s, c;
        sincosf(p, &s, &c);
        my_s[tid] = s; my_c[tid] = c;
        g_sc[0][rowbase + tid] = make_float2(s, c);
        __threadfence();
    }
    __syncthreads();
    if (tid == 0) ((volatile int*)g_flags)[bid * FLAG_STRIDE] = 1;
    const float scale = sh_scale;

    const int group  = warp >> 1;       // 0..3 : 8-row group
    const int half_  = warp & 1;        // 0/1  : column half
    const int wr0    = rowbase + group * 8;
    const int cstart = half_ * 2048;
    const __half* Wb = g_W + ((size_t)wr0 << 12);

    for (int sample = 0; sample < 4; sample++) {
        if (tid < 32) ext_sm[tid] = g_ext[sample][rowbase + tid];

        #pragma unroll 1
        for (int it = 0; it < 100; it++) {
            const int t = sample * 100 + it + 1;   // global step 1..400

            // ---- wait for all producers of step t-1 (also frees buffer t&1) ----
            if (tid < NB) {
                while (((volatile int*)g_flags)[tid * FLAG_STRIDE] < t) { }
            }
            __syncthreads();

            // ---- stage full (s,c) vector from L2 into padded smem ----
            const float4* src = (const float4*)g_sc[(t - 1) & 1];
            #pragma unroll
            for (int i = 0; i < 8; i++) {
                int j = tid + i * 256;             // 0..2047
                float4 v = __ldcg(src + j);
                int c0 = j * 2;
                s_sm[padi(c0)]     = v.x;  c_sm[padi(c0)]     = v.y;
                s_sm[padi(c0 + 1)] = v.z;  c_sm[padi(c0 + 1)] = v.w;
            }
            __syncthreads();

            // ---- 8 rows x 2048 cols per warp: W@s and W@c ----
            float accS[8], accC[8];
            #pragma unroll
            for (int r = 0; r < 8; r++) { accS[r] = 0.f; accC[r] = 0.f; }

            #pragma unroll 1
            for (int chunk = 0; chunk < 8; chunk++) {
                const int cb = cstart + (chunk << 8) + (lane << 3);
                const int pb = cb + (cb >> 3);
                float sv[8], cv[8];
                #pragma unroll
                for (int m = 0; m < 8; m++) { sv[m] = s_sm[pb + m]; cv[m] = c_sm[pb + m]; }
                #pragma unroll
                for (int r = 0; r < 8; r++) {
                    const uint4 w = *(const uint4*)(Wb + ((size_t)r << 12) + cb);
                    float2 f;
                    f = __half22float2(*(const __half2*)&w.x);
                    accS[r] += f.x * sv[0] + f.y * sv[1];
                    accC[r] += f.x * cv[0] + f.y * cv[1];
                    f = __half22float2(*(const __half2*)&w.y);
                    accS[r] += f.x * sv[2] + f.y * sv[3];
                    accC[r] += f.x * cv[2] + f.y * cv[3];
                    f = __half22float2(*(const __half2*)&w.z);
                    accS[r] += f.x * sv[4] + f.y * sv[5];
                    accC[r] += f.x * cv[4] + f.y * cv[5];
                    f = __half22float2(*(const __half2*)&w.w);
                    accS[r] += f.x * sv[6] + f.y * sv[7];
                    accC[r] += f.x * cv[6] + f.y * cv[7];
                }
            }

            // ---- butterfly reduce over lanes, combine column halves ----
            #pragma unroll
            for (int r = 0; r < 8; r++) {
                #pragma unroll
                for (int off = 16; off; off >>= 1) {
                    accS[r] += __shfl_xor_sync(0xffffffffu, accS[r], off);
                    accC[r] += __shfl_xor_sync(0xffffffffu, accC[r], off);
                }
            }
            if (lane == 0) {
                #pragma unroll
                for (int r = 0; r < 8; r++) {
                    redS[half_][group][r] = accS[r];
                    redC[half_][group][r] = accC[r];
                }
            }
            __syncthreads();

            // ---- phi update for this block's 32 rows ----
            if (tid < 32) {
                int g = tid >> 3, r = tid & 7;
                float Ws = redS[0][g][r] + redS[1][g][r];
                float Wc = redC[0][g][r] + redC[1][g][r];
                float si = my_s[tid], ci = my_c[tid];
                float coup = ci * Ws - si * Wc;
                float p = phi_sm[tid] + DT_C * (om_sm[tid] + scale * coup + ext_sm[tid]);
                p = p - floorf(p * INV_TWO_PI_F) * TWO_PI_F;   // jnp.mod(p, 2pi)
                phi_sm[tid] = p;
                float s, c;
                sincosf(p, &s, &c);
                my_s[tid] = s; my_c[tid] = c;
                g_sc[t & 1][rowbase + tid] = make_float2(s, c);
                __threadfence();
            }
            __syncthreads();
            if (tid == 0) ((volatile int*)g_flags)[bid * FLAG_STRIDE] = t + 1;
        }

        // ---- readout: fold this block's 64 features into logits ----
        // feats[j] = sin(phi_j) (j<N), cos(phi_{j-N}) (j>=N); only our 32 rows.
        {
            float p0 = 0.f, p1 = 0.f, p2 = 0.f, p3 = 0.f;
            const int c0 = tid, c1 = tid + 256, c2 = tid + 512, c3 = tid + 768;
            const bool has3 = (c3 < 1000);
            #pragma unroll 1
            for (int j = 0; j < 32; j++) {
                float sj = my_s[j], cj = my_c[j];
                const float* rwS = readout_w + (size_t)(rowbase + j) * 1000;
                const float* rwC = readout_w + (size_t)(N_OSC + rowbase + j) * 1000;
                p0 += sj * rwS[c0] + cj * rwC[c0];
                p1 += sj * rwS[c1] + cj * rwC[c1];
                p2 += sj * rwS[c2] + cj * rwC[c2];
                if (has3) p3 += sj * rwS[c3] + cj * rwC[c3];
            }
            float* ob = out + sample * 1000;
            atomicAdd(ob + c0, p0);
            atomicAdd(ob + c1, p1);
            atomicAdd(ob + c2, p2);
            if (has3) atomicAdd(ob + c3, p3);
        }
    }
}

// ---------------- launch ----------------
extern "C" void kernel_launch(void* const* d_in, const int* in_sizes, int n_in,
                              void* d_out, int out_size) {
    const float* x     = (const float*)d_in[0];   // [4,2048]
    const float* enc_w = (const float*)d_in[1];   // [2048,4096]
    const float* enc_b = (const float*)d_in[2];   // [4096]
    const float* rw    = (const float*)d_in[3];   // [8192,1000]
    const float* rb    = (const float*)d_in[4];   // [1000]
    const float* omega = (const float*)d_in[5];   // [4096]
    const float* adjl  = (const float*)d_in[6];   // [4096,4096]
    const float* cplm  = (const float*)d_in[7];   // [4096,4096]
    const float* kstr  = (const float*)d_in[8];   // [1]
    const float* iphi  = (const float*)d_in[9];   // [4096]
    float* out = (float*)d_out;                   // [4,1000] fp32

    prep_kernel<<<16, 256>>>(out, rb);
    build_w_kernel<<<16384, 256>>>(adjl, cplm);
    encoder_kernel<<<16, 256>>>(x, enc_w, enc_b);
    kuramoto_kernel<<<NB, 256>>>(omega, iphi, kstr, rw, out);
}

// round 4
// speedup vs baseline: 1.0864x; 1.0864x over previous
#include <cuda_runtime.h>
#include <cuda_fp16.h>
#include <cstdint>
#include <cstddef>

#define N_OSC 4096
#define NB 128               // persistent blocks (one per SM)
#define THREADS 512
#define FLAG_STRIDE 32
#define ROW_CA 22            // rows per block kept L1-resident via __ldca (22*8KB=176KB)
#define DT_C 0.01f
#define TWO_PI_F 6.283185307179586f
#define INV_TWO_PI_F 0.15915494309189535f

// padded smem half index: stride-32B warp reads become conflict-free
#define PADH(i) ((i) + (((i) >> 6) << 3))

// ---------------- device scratch (static, no allocation) ----------------
__device__ __half g_W[(size_t)N_OSC * N_OSC];   // 32 MB effective coupling, fp16 row-major
__device__ __half g_s[2][N_OSC];                // double-buffered sin (fp16)
__device__ __half g_c[2][N_OSC];                // double-buffered cos (fp16)
__device__ float  g_ext[4][N_OSC];              // tanh(x@enc_w+enc_b)
__device__ int    g_flags[NB * FLAG_STRIDE];    // per-block progress flags

// ---------------- prep: zero flags, write bias into output ----------------
__global__ void prep_kernel(float* __restrict__ out, const float* __restrict__ rb) {
    int i = blockIdx.x * blockDim.x + threadIdx.x;
    if (i < NB) g_flags[i * FLAG_STRIDE] = 0;
    if (i < 4000) out[i] = rb[i % 1000];
}

// ---------------- W = sigmoid(adj_logits) * (1-eye) * coupling, fp16 ------
__global__ void build_w_kernel(const float* __restrict__ adj, const float* __restrict__ cpl) {
    size_t idx  = (size_t)blockIdx.x * blockDim.x + threadIdx.x;
    size_t base = idx * 4;
    float4 a = ((const float4*)adj)[idx];
    float4 k = ((const float4*)cpl)[idx];
    int row = (int)(base >> 12);
    int col = (int)(base & 4095);
    float w0 = k.x / (1.0f + expf(-a.x));
    float w1 = k.y / (1.0f + expf(-a.y));
    float w2 = k.z / (1.0f + expf(-a.z));
    float w3 = k.w / (1.0f + expf(-a.w));
    if (col     == row) w0 = 0.0f;
    if (col + 1 == row) w1 = 0.0f;
    if (col + 2 == row) w2 = 0.0f;
    if (col + 3 == row) w3 = 0.0f;
    __half2* o = (__half2*)(g_W + base);
    o[0] = __floats2half2_rn(w0, w1);
    o[1] = __floats2half2_rn(w2, w3);
}

// ---------------- ext = tanh(x @ enc_w + enc_b), [4, 4096] ----------------
__global__ void encoder_kernel(const float* __restrict__ x,
                               const float* __restrict__ enc_w,
                               const float* __restrict__ enc_b) {
    __shared__ float xs[4 * 2048];
    int tid = threadIdx.x;
    for (int i = tid; i < 8192; i += 256) xs[i] = x[i];
    __syncthreads();
    int n = blockIdx.x * 256 + tid;
    float a0 = 0.f, a1 = 0.f, a2 = 0.f, a3 = 0.f;
    for (int d = 0; d < 2048; d++) {
        float w = enc_w[(size_t)d * N_OSC + n];
        a0 += xs[d]        * w;
        a1 += xs[2048 + d] * w;
        a2 += xs[4096 + d] * w;
        a3 += xs[6144 + d] * w;
    }
    float b = enc_b[n];
    g_ext[0][n] = tanhf(a0 + b);
    g_ext[1][n] = tanhf(a1 + b);
    g_ext[2][n] = tanhf(a2 + b);
    g_ext[3][n] = tanhf(a3 + b);
}

// ---------------- persistent Kuramoto integrator + readout ----------------
__global__ void __launch_bounds__(THREADS, 1)
kuramoto_kernel(const float* __restrict__ omega,
                const float* __restrict__ init_phases,
                const float* __restrict__ kstr,
                const float* __restrict__ readout_w,
                float* __restrict__ out) {
    __shared__ __half s_h[4608], c_h[4608];           // padded fp16 sin/cos vectors
    __shared__ float redS[4][4][8], redC[4][4][8];    // [quarter][group][row]
    __shared__ float my_s[32], my_c[32], phi_sm[32], om_sm[32], ext_sm[32];
    __shared__ float sh_scale;

    const int tid  = threadIdx.x;
    const int bid  = blockIdx.x;
    const int lane = tid & 31;
    const int warp = tid >> 5;
    const int rowbase = bid * 32;

    // ---- init: phases, omega, initial fp16 sin/cos published to buffer 0 ----
    if (tid == 0) sh_scale = kstr[0] * (1.0f / (float)N_OSC);
    if (tid < 32) {
        float p = init_phases[rowbase + tid];
        phi_sm[tid] = p;
        om_sm[tid]  = omega[rowbase + tid];
        float s, c;
        sincosf(p, &s, &c);
        my_s[tid] = s; my_c[tid] = c;
        g_s[0][rowbase + tid] = __float2half_rn(s);
        g_c[0][rowbase + tid] = __float2half_rn(c);
        __threadfence();
    }
    __syncthreads();
    if (tid == 0) ((volatile int*)g_flags)[bid * FLAG_STRIDE] = 1;
    const float scale = sh_scale;

    const int qid = warp & 3;            // column quarter (1024 cols)
    const int grp = warp >> 2;           // 0..3 : 8-row group
    const int wr0 = rowbase + grp * 8;
    const int cstart = qid * 1024;
    const __half* Wb = g_W + ((size_t)wr0 << 12);
    const __half2 h2z = __float2half2_rn(0.0f);

    for (int sample = 0; sample < 4; sample++) {
        if (tid < 32) ext_sm[tid] = g_ext[sample][rowbase + tid];

        #pragma unroll 1
        for (int it = 0; it < 100; it++) {
            const int t = sample * 100 + it + 1;   // global step 1..400

            // ---- wait for all producers of step t-1 (also frees buffer t&1) ----
            if (tid < NB) {
                while (((volatile int*)g_flags)[tid * FLAG_STRIDE] < t) { }
            }
            __syncthreads();

            // ---- stage fp16 (s, c) vectors from L2 into padded smem ----
            {
                const uint4* ps = (const uint4*)(g_s[(t - 1) & 1]);
                const uint4* pc = (const uint4*)(g_c[(t - 1) & 1]);
                uint4 vs = __ldcg(ps + tid);
                uint4 vc = __ldcg(pc + tid);
                int col0 = tid * 8;
                *(uint4*)(s_h + PADH(col0)) = vs;
                *(uint4*)(c_h + PADH(col0)) = vc;
            }
            __syncthreads();

            // ---- 8 rows x 1024 cols per warp: W@s and W@c (HFMA2) ----
            float accS[8], accC[8];
            #pragma unroll
            for (int r = 0; r < 8; r++) { accS[r] = 0.f; accC[r] = 0.f; }

            #pragma unroll
            for (int ch = 0; ch < 2; ch++) {
                const int cb = cstart + (ch << 9) + (lane << 4);   // 16 cols
                const int pb = PADH(cb);
                __half2 sv[8], cv[8];
                *(uint4*)(sv)     = *(const uint4*)(s_h + pb);
                *(uint4*)(sv + 4) = *(const uint4*)(s_h + pb + 8);
                *(uint4*)(cv)     = *(const uint4*)(c_h + pb);
                *(uint4*)(cv + 4) = *(const uint4*)(c_h + pb + 8);

                #pragma unroll
                for (int r = 0; r < 8; r++) {
                    const uint4* wq = (const uint4*)(Wb + ((size_t)r << 12) + cb);
                    uint4 wA, wB;
                    if (grp * 8 + r < ROW_CA) { wA = __ldca(wq); wB = __ldca(wq + 1); }
                    else                      { wA = __ldcg(wq); wB = __ldcg(wq + 1); }
                    __half2 wv[8];
                    *(uint4*)(wv)     = wA;
                    *(uint4*)(wv + 4) = wB;
                    __half2 hS = h2z, hC = h2z;
                    #pragma unroll
                    for (int k = 0; k < 8; k++) {
                        hS = __hfma2(wv[k], sv[k], hS);
                        hC = __hfma2(wv[k], cv[k], hC);
                    }
                    float2 fS = __half22float2(hS);
                    float2 fC = __half22float2(hC);
                    accS[r] += fS.x + fS.y;
                    accC[r] += fC.x + fC.y;
                }
            }

            // ---- butterfly reduce over lanes, stash per-quarter partials ----
            #pragma unroll
            for (int r = 0; r < 8; r++) {
                #pragma unroll
                for (int off = 16; off; off >>= 1) {
                    accS[r] += __shfl_xor_sync(0xffffffffu, accS[r], off);
                    accC[r] += __shfl_xor_sync(0xffffffffu, accC[r], off);
                }
            }
            if (lane == 0) {
                #pragma unroll
                for (int r = 0; r < 8; r++) {
                    redS[qid][grp][r] = accS[r];
                    redC[qid][grp][r] = accC[r];
                }
            }
            __syncthreads();

            // ---- phi update for this block's 32 rows (fp32) ----
            if (tid < 32) {
                int g = tid >> 3, r = tid & 7;
                float Ws = redS[0][g][r] + redS[1][g][r] + redS[2][g][r] + redS[3][g][r];
                float Wc = redC[0][g][r] + redC[1][g][r] + redC[2][g][r] + redC[3][g][r];
                float si = my_s[tid], ci = my_c[tid];
                float coup = ci * Ws - si * Wc;
                float p = phi_sm[tid] + DT_C * (om_sm[tid] + scale * coup + ext_sm[tid]);
                p = p - floorf(p * INV_TWO_PI_F) * TWO_PI_F;   // jnp.mod(p, 2pi)
                phi_sm[tid] = p;
                float s, c;
                sincosf(p, &s, &c);
                my_s[tid] = s; my_c[tid] = c;
                g_s[t & 1][rowbase + tid] = __float2half_rn(s);
                g_c[t & 1][rowbase + tid] = __float2half_rn(c);
                __threadfence();
            }
            __syncthreads();
            if (tid == 0) ((volatile int*)g_flags)[bid * FLAG_STRIDE] = t + 1;
        }

        // ---- readout: fold this block's 64 features into logits ----
        {
            float p0 = 0.f, p1 = 0.f;
            const int c0 = tid;            // always < 1000 (tid < 512)
            const int c1 = tid + 512;
            const bool h1 = (c1 < 1000);
            #pragma unroll 1
            for (int j = 0; j < 32; j++) {
                float sj = my_s[j], cj = my_c[j];
                const float* rwS = readout_w + (size_t)(rowbase + j) * 1000;
                const float* rwC = readout_w + (size_t)(N_OSC + rowbase + j) * 1000;
                p0 += sj * rwS[c0] + cj * rwC[c0];
                if (h1) p1 += sj * rwS[c1] + cj * rwC[c1];
            }
            float* ob = out + sample * 1000;
            atomicAdd(ob + c0, p0);
            if (h1) atomicAdd(ob + c1, p1);
        }
    }
}

// ---------------- launch ----------------
extern "C" void kernel_launch(void* const* d_in, const int* in_sizes, int n_in,
                              void* d_out, int out_size) {
    const float* x     = (const float*)d_in[0];   // [4,2048]
    const float* enc_w = (const float*)d_in[1];   // [2048,4096]
    const float* enc_b = (const float*)d_in[2];   // [4096]
    const float* rw    = (const float*)d_in[3];   // [8192,1000]
    const float* rb    = (const float*)d_in[4];   // [1000]
    const float* omega = (const float*)d_in[5];   // [4096]
    const float* adjl  = (const float*)d_in[6];   // [4096,4096]
    const float* cplm  = (const float*)d_in[7];   // [4096,4096]
    const float* kstr  = (const float*)d_in[8];   // [1]
    const float* iphi  = (const float*)d_in[9];   // [4096]
    float* out = (float*)d_out;                   // [4,1000] fp32

    prep_kernel<<<16, 256>>>(out, rb);
    build_w_kernel<<<16384, 256>>>(adjl, cplm);
    encoder_kernel<<<16, 256>>>(x, enc_w, enc_b);
    kuramoto_kernel<<<NB, THREADS>>>(omega, iphi, kstr, rw, out);
}

// round 5
// speedup vs baseline: 1.4396x; 1.3251x over previous
#include <cuda_runtime.h>
#include <cuda_fp16.h>
#include <cstdint>
#include <cstddef>

#define N_OSC 4096
#define NB 128               // persistent blocks (one per SM)
#define THREADS 512
#define DT_C 0.01f
#define TWO_PI_F 6.283185307179586f
#define INV_TWO_PI_F 0.15915494309189535f

// padded smem half index: stride-32B warp reads become conflict-free
#define PADH(i) ((i) + (((i) >> 6) << 3))

// ---------------- device scratch (static, no allocation) ----------------
__device__ uint8_t  g_W[(size_t)N_OSC * N_OSC];  // 16 MB effective coupling, e4m3 row-major
__device__ __half   g_s[2][N_OSC];               // double-buffered sin (fp16)
__device__ __half   g_c[2][N_OSC];               // double-buffered cos (fp16)
__device__ float    g_ext[4][N_OSC];             // tanh(x@enc_w+enc_b)
__device__ unsigned g_arrive;                    // global arrival counter

// e4m3x4 (packed in u32) -> 2x half2
__device__ __forceinline__ void cvt_fp8x4(uint32_t v, __half2& a, __half2& b) {
    uint32_t ra, rb;
    asm("{\n\t.reg .b16 lo, hi;\n\t"
        "mov.b32 {lo, hi}, %2;\n\t"
        "cvt.rn.f16x2.e4m3x2 %0, lo;\n\t"
        "cvt.rn.f16x2.e4m3x2 %1, hi;\n\t}"
        : "=r"(ra), "=r"(rb) : "r"(v));
    a = *(__half2*)&ra;
    b = *(__half2*)&rb;
}

// ---------------- prep: zero counter, write bias into output ----------------
__global__ void prep_kernel(float* __restrict__ out, const float* __restrict__ rb) {
    int i = blockIdx.x * blockDim.x + threadIdx.x;
    if (i == 0) g_arrive = 0u;
    if (i < 4000) out[i] = rb[i % 1000];
}

// ---------------- W = sigmoid(adj_logits) * (1-eye) * coupling, e4m3 ------
__global__ void build_w_kernel(const float* __restrict__ adj, const float* __restrict__ cpl) {
    size_t idx  = (size_t)blockIdx.x * blockDim.x + threadIdx.x;
    size_t base = idx * 4;
    float4 a = ((const float4*)adj)[idx];
    float4 k = ((const float4*)cpl)[idx];
    int row = (int)(base >> 12);
    int col = (int)(base & 4095);
    float w0 = k.x / (1.0f + expf(-a.x));
    float w1 = k.y / (1.0f + expf(-a.y));
    float w2 = k.z / (1.0f + expf(-a.z));
    float w3 = k.w / (1.0f + expf(-a.w));
    if (col     == row) w0 = 0.0f;
    if (col + 1 == row) w1 = 0.0f;
    if (col + 2 == row) w2 = 0.0f;
    if (col + 3 == row) w3 = 0.0f;
    unsigned short p01, p23;
    asm("cvt.rn.satfinite.e4m3x2.f32 %0, %1, %2;" : "=h"(p01) : "f"(w1), "f"(w0));
    asm("cvt.rn.satfinite.e4m3x2.f32 %0, %1, %2;" : "=h"(p23) : "f"(w3), "f"(w2));
    ((uint32_t*)g_W)[idx] = (uint32_t)p01 | ((uint32_t)p23 << 16);
}

// ---------------- ext = tanh(x @ enc_w + enc_b), [4, 4096] ----------------
// 128 blocks; block owns 32 n-columns; 8 d-partitions of 256 per thread group.
__global__ void encoder_kernel(const float* __restrict__ x,
                               const float* __restrict__ enc_w,
                               const float* __restrict__ enc_b) {
    __shared__ float xs[4 * 2048];
    __shared__ float part[8][4][32];
    int tid = threadIdx.x;
    for (int i = tid; i < 8192; i += 256) xs[i] = x[i];
    __syncthreads();
    int nloc  = tid & 31;                 // 0..31 column within block
    int dpart = tid >> 5;                 // 0..7 d-partition
    int n = blockIdx.x * 32 + nloc;
    float a0 = 0.f, a1 = 0.f, a2 = 0.f, a3 = 0.f;
    int d0 = dpart * 256;
    for (int k = 0; k < 256; k++) {
        int d = d0 + k;
        float w = enc_w[(size_t)d * N_OSC + n];
        a0 += xs[d]        * w;
        a1 += xs[2048 + d] * w;
        a2 += xs[4096 + d] * w;
        a3 += xs[6144 + d] * w;
    }
    part[dpart][0][nloc] = a0;
    part[dpart][1][nloc] = a1;
    part[dpart][2][nloc] = a2;
    part[dpart][3][nloc] = a3;
    __syncthreads();
    if (tid < 128) {
        int s = tid >> 5, nl = tid & 31;
        float acc = enc_b[blockIdx.x * 32 + nl];
        #pragma unroll
        for (int p = 0; p < 8; p++) acc += part[p][s][nl];
        g_ext[s][blockIdx.x * 32 + nl] = tanhf(acc);
    }
}

// ---------------- persistent Kuramoto integrator + readout ----------------
__global__ void __launch_bounds__(THREADS, 1)
kuramoto_kernel(const float* __restrict__ omega,
                const float* __restrict__ init_phases,
                const float* __restrict__ kstr,
                const float* __restrict__ readout_w,
                float* __restrict__ out) {
    __shared__ __half s_h[4608], c_h[4608];           // padded fp16 sin/cos vectors
    __shared__ float redS[4][4][8], redC[4][4][8];    // [quarter][group][row]
    __shared__ float my_s[32], my_c[32], phi_sm[32], om_sm[32], ext_sm[32];
    __shared__ float sh_scale;

    const int tid  = threadIdx.x;
    const int bid  = blockIdx.x;
    const int lane = tid & 31;
    const int warp = tid >> 5;
    const int rowbase = bid * 32;

    // ---- init: phases, omega, initial fp16 sin/cos published to buffer 0 ----
    if (tid == 0) sh_scale = kstr[0] * (1.0f / (float)N_OSC);
    if (tid < 32) {
        float p = init_phases[rowbase + tid];
        phi_sm[tid] = p;
        om_sm[tid]  = omega[rowbase + tid];
        float s, c;
        sincosf(p, &s, &c);
        my_s[tid] = s; my_c[tid] = c;
        g_s[0][rowbase + tid] = __float2half_rn(s);
        g_c[0][rowbase + tid] = __float2half_rn(c);
    }
    __syncthreads();
    if (tid == 0) { __threadfence(); atomicAdd(&g_arrive, 1u); }
    const float scale = sh_scale;

    const int qid = warp & 3;            // column quarter (1024 cols)
    const int grp = warp >> 2;           // 0..3 : 8-row group
    const int wr0 = rowbase + grp * 8;
    const int cstart = qid * 1024;
    const uint8_t* Wb = g_W + ((size_t)wr0 << 12);
    const __half2 h2z = __float2half2_rn(0.0f);

    for (int sample = 0; sample < 4; sample++) {
        if (tid < 32) ext_sm[tid] = g_ext[sample][rowbase + tid];

        #pragma unroll 1
        for (int it = 0; it < 100; it++) {
            const int t = sample * 100 + it + 1;   // global step 1..400

            // ---- wait until all NB blocks published step t-1 ----
            if (tid == 0) {
                while (*(volatile unsigned*)&g_arrive < (unsigned)(t * NB)) { }
                __threadfence();   // acquire: order subsequent reads after observed stores
            }
            __syncthreads();

            // ---- stage fp16 (s, c) vectors from L2 into padded smem ----
            {
                const uint4* ps = (const uint4*)(g_s[(t - 1) & 1]);
                const uint4* pc = (const uint4*)(g_c[(t - 1) & 1]);
                uint4 vs = __ldcg(ps + tid);
                uint4 vc = __ldcg(pc + tid);
                int col0 = tid * 8;
                *(uint4*)(s_h + PADH(col0)) = vs;
                *(uint4*)(c_h + PADH(col0)) = vc;
            }
            __syncthreads();

            // ---- 8 rows x 1024 cols per warp: W@s and W@c (e4m3 -> HFMA2) ----
            float accS[8], accC[8];
            #pragma unroll
            for (int r = 0; r < 8; r++) { accS[r] = 0.f; accC[r] = 0.f; }

            #pragma unroll
            for (int ch = 0; ch < 2; ch++) {
                const int cb = cstart + (ch << 9) + (lane << 4);   // 16 cols
                const int pb = PADH(cb);
                __half2 sv[8], cv[8];
                *(uint4*)(sv)     = *(const uint4*)(s_h + pb);
                *(uint4*)(sv + 4) = *(const uint4*)(s_h + pb + 8);
                *(uint4*)(cv)     = *(const uint4*)(c_h + pb);
                *(uint4*)(cv + 4) = *(const uint4*)(c_h + pb + 8);

                #pragma unroll
                for (int r = 0; r < 8; r++) {
                    // 16 fp8 weights = one uint4; L1-resident (128KB slice/SM)
                    const uint4 w = __ldca((const uint4*)(Wb + ((size_t)r << 12) + cb));
                    __half2 wv[8];
                    cvt_fp8x4(w.x, wv[0], wv[1]);
                    cvt_fp8x4(w.y, wv[2], wv[3]);
                    cvt_fp8x4(w.z, wv[4], wv[5]);
                    cvt_fp8x4(w.w, wv[6], wv[7]);
                    __half2 hS = h2z, hC = h2z;
                    #pragma unroll
                    for (int k = 0; k < 8; k++) {
                        hS = __hfma2(wv[k], sv[k], hS);
                        hC = __hfma2(wv[k], cv[k], hC);
                    }
                    float2 fS = __half22float2(hS);
                    float2 fC = __half22float2(hC);
                    accS[r] += fS.x + fS.y;
                    accC[r] += fC.x + fC.y;
                }
            }

            // ---- butterfly reduce over lanes, stash per-quarter partials ----
            #pragma unroll
            for (int r = 0; r < 8; r++) {
                #pragma unroll
                for (int off = 16; off; off >>= 1) {
                    accS[r] += __shfl_xor_sync(0xffffffffu, accS[r], off);
                    accC[r] += __shfl_xor_sync(0xffffffffu, accC[r], off);
                }
            }
            if (lane == 0) {
                #pragma unroll
                for (int r = 0; r < 8; r++) {
                    redS[qid][grp][r] = accS[r];
                    redC[qid][grp][r] = accC[r];
                }
            }
            __syncthreads();

            // ---- phi update for this block's 32 rows (fp32) ----
            if (tid < 32) {
                int g = tid >> 3, r = tid & 7;
                float Ws = redS[0][g][r] + redS[1][g][r] + redS[2][g][r] + redS[3][g][r];
                float Wc = redC[0][g][r] + redC[1][g][r] + redC[2][g][r] + redC[3][g][r];
                float si = my_s[tid], ci = my_c[tid];
                float coup = ci * Ws - si * Wc;
                float p = phi_sm[tid] + DT_C * (om_sm[tid] + scale * coup + ext_sm[tid]);
                p = p - floorf(p * INV_TWO_PI_F) * TWO_PI_F;   // jnp.mod(p, 2pi)
                phi_sm[tid] = p;
                float s, c;
                __sincosf(p, &s, &c);
                my_s[tid] = s; my_c[tid] = c;
                g_s[t & 1][rowbase + tid] = __float2half_rn(s);
                g_c[t & 1][rowbase + tid] = __float2half_rn(c);
            }
            __syncthreads();
            if (tid == 0) { __threadfence(); atomicAdd(&g_arrive, 1u); }
        }

        // ---- readout: fold this block's 64 features into logits ----
        {
            float p0 = 0.f, p1 = 0.f;
            const int c0 = tid;            // always < 1000 (tid < 512)
            const int c1 = tid + 512;
            const bool h1 = (c1 < 1000);
            #pragma unroll 1
            for (int j = 0; j < 32; j++) {
                float sj = my_s[j], cj = my_c[j];
                const float* rwS = readout_w + (size_t)(rowbase + j) * 1000;
                const float* rwC = readout_w + (size_t)(N_OSC + rowbase + j) * 1000;
                p0 += sj * rwS[c0] + cj * rwC[c0];
                if (h1) p1 += sj * rwS[c1] + cj * rwC[c1];
            }
            float* ob = out + sample * 1000;
            atomicAdd(ob + c0, p0);
            if (h1) atomicAdd(ob + c1, p1);
        }
    }
}

// ---------------- launch ----------------
extern "C" void kernel_launch(void* const* d_in, const int* in_sizes, int n_in,
                              void* d_out, int out_size) {
    const float* x     = (const float*)d_in[0];   // [4,2048]
    const float* enc_w = (const float*)d_in[1];   // [2048,4096]
    const float* enc_b = (const float*)d_in[2];   // [4096]
    const float* rw    = (const float*)d_in[3];   // [8192,1000]
    const float* rb    = (const float*)d_in[4];   // [1000]
    const float* omega = (const float*)d_in[5];   // [4096]
    const float* adjl  = (const float*)d_in[6];   // [4096,4096]
    const float* cplm  = (const float*)d_in[7];   // [4096,4096]
    const float* kstr  = (const float*)d_in[8];   // [1]
    const float* iphi  = (const float*)d_in[9];   // [4096]
    float* out = (float*)d_out;                   // [4,1000] fp32

    prep_kernel<<<16, 256>>>(out, rb);
    build_w_kernel<<<16384, 256>>>(adjl, cplm);
    encoder_kernel<<<128, 256>>>(x, enc_w, enc_b);
    kuramoto_kernel<<<NB, THREADS>>>(omega, iphi, kstr, rw, out);
}

// round 6
// speedup vs baseline: 2.0360x; 1.4143x over previous
#include <cuda_runtime.h>
#include <cuda_fp16.h>
#include <cstdint>
#include <cstddef>

#define N_OSC 4096
#define NB 128               // persistent blocks (one per SM)
#define THREADS 512
#define DT_C 0.01f
#define TWO_PI_F 6.283185307179586f
#define INV_TWO_PI_F 0.15915494309189535f

// dynamic smem layout
#define W_BYTES_PER_BLOCK 131072u            // 32 rows * 4096 cols e4m3, fragment order
#define SC_S_OFF 131072u                     // 4096 B of s (e4m3)
#define SC_C_OFF (131072u + 4160u)           // 4096 B of c (e4m3), +64B pad kills bank overlap
#define RED_OFF  (131072u + 8320u)           // 2 * 1024 B reduction scratch
#define DYN_SMEM (RED_OFF + 2048u + 64u)

// ---------------- device scratch (static, no allocation) ----------------
__device__ uint8_t  g_W [(size_t)N_OSC * N_OSC];  // e4m3, linear row-major (intermediate)
__device__ uint8_t  g_Wf[(size_t)N_OSC * N_OSC];  // e4m3, mma A-fragment order
__device__ uint8_t  g_sc8[2][8192];               // double-buffered: [0,4096)=sin e4m3, [4096,8192)=cos
__device__ float    g_ext[4][N_OSC];              // tanh(x@enc_w+enc_b)
__device__ unsigned g_arrive;                     // global arrival counter

// m16n8k32 e4m3 x e4m3 -> f32 accumulate
__device__ __forceinline__ void mma_e4m3(float4& d, const uint4& a, uint32_t b0, uint32_t b1) {
    asm volatile(
        "mma.sync.aligned.m16n8k32.row.col.f32.e4m3.e4m3.f32 "
        "{%0,%1,%2,%3}, {%4,%5,%6,%7}, {%8,%9}, {%0,%1,%2,%3};\n"
        : "+f"(d.x), "+f"(d.y), "+f"(d.z), "+f"(d.w)
        : "r"(a.x), "r"(a.y), "r"(a.z), "r"(a.w), "r"(b0), "r"(b1));
}

// ---------------- prep: zero counter, write bias into output ----------------
__global__ void prep_kernel(float* __restrict__ out, const float* __restrict__ rb) {
    int i = blockIdx.x * blockDim.x + threadIdx.x;
    if (i == 0) g_arrive = 0u;
    if (i < 4000) out[i] = rb[i % 1000];
}

// ---------------- W = sigmoid(adj_logits) * (1-eye) * coupling, e4m3 ------
__global__ void build_w_kernel(const float* __restrict__ adj, const float* __restrict__ cpl) {
    size_t idx  = (size_t)blockIdx.x * blockDim.x + threadIdx.x;
    size_t base = idx * 4;
    float4 a = ((const float4*)adj)[idx];
    float4 k = ((const float4*)cpl)[idx];
    int row = (int)(base >> 12);
    int col = (int)(base & 4095);
    float w0 = k.x / (1.0f + expf(-a.x));
    float w1 = k.y / (1.0f + expf(-a.y));
    float w2 = k.z / (1.0f + expf(-a.z));
    float w3 = k.w / (1.0f + expf(-a.w));
    if (col     == row) w0 = 0.0f;
    if (col + 1 == row) w1 = 0.0f;
    if (col + 2 == row) w2 = 0.0f;
    if (col + 3 == row) w3 = 0.0f;
    unsigned short p01, p23;
    asm("cvt.rn.satfinite.e4m3x2.f32 %0, %1, %2;" : "=h"(p01) : "f"(w1), "f"(w0));
    asm("cvt.rn.satfinite.e4m3x2.f32 %0, %1, %2;" : "=h"(p23) : "f"(w3), "f"(w2));
    ((uint32_t*)g_W)[idx] = (uint32_t)p01 | ((uint32_t)p23 << 16);
}

// ---------------- relayout linear e4m3 W -> mma A-fragment order ----------
// frag index f = ((bid*2 + mt)*128 + kc)*32 + lane ; each thread emits one uint4:
//   .x = A[row0  ][col0..+3]  .y = A[row0+8][col0..+3]
//   .z = A[row0  ][col0+16..] .w = A[row0+8][col0+16..]
__global__ void relayout_kernel() {
    int f    = blockIdx.x * blockDim.x + threadIdx.x;   // 0 .. 2^20-1
    int bid  = f >> 13;
    int r    = f & 8191;
    int mt   = r >> 12;
    int kc   = (r >> 5) & 127;
    int lane = r & 31;
    int row0 = bid * 32 + mt * 16 + (lane >> 2);
    int col0 = kc * 32 + (lane & 3) * 4;
    uint4 v;
    v.x = *(const uint32_t*)(g_W + (size_t)row0       * 4096 + col0);
    v.y = *(const uint32_t*)(g_W + (size_t)(row0 + 8) * 4096 + col0);
    v.z = *(const uint32_t*)(g_W + (size_t)row0       * 4096 + col0 + 16);
    v.w = *(const uint32_t*)(g_W + (size_t)(row0 + 8) * 4096 + col0 + 16);
    ((uint4*)g_Wf)[f] = v;
}

// ---------------- ext = tanh(x @ enc_w + enc_b), [4, 4096] ----------------
__global__ void encoder_kernel(const float* __restrict__ x,
                               const float* __restrict__ enc_w,
                               const float* __restrict__ enc_b) {
    __shared__ float xs[4 * 2048];
    __shared__ float part[8][4][32];
    int tid = threadIdx.x;
    for (int i = tid; i < 8192; i += 256) xs[i] = x[i];
    __syncthreads();
    int nloc  = tid & 31;
    int dpart = tid >> 5;
    int n = blockIdx.x * 32 + nloc;
    float a0 = 0.f, a1 = 0.f, a2 = 0.f, a3 = 0.f;
    int d0 = dpart * 256;
    for (int k = 0; k < 256; k++) {
        int d = d0 + k;
        float w = enc_w[(size_t)d * N_OSC + n];
        a0 += xs[d]        * w;
        a1 += xs[2048 + d] * w;
        a2 += xs[4096 + d] * w;
        a3 += xs[6144 + d] * w;
    }
    part[dpart][0][nloc] = a0;
    part[dpart][1][nloc] = a1;
    part[dpart][2][nloc] = a2;
    part[dpart][3][nloc] = a3;
    __syncthreads();
    if (tid < 128) {
        int s = tid >> 5, nl = tid & 31;
        float acc = enc_b[blockIdx.x * 32 + nl];
        #pragma unroll
        for (int p = 0; p < 8; p++) acc += part[p][s][nl];
        g_ext[s][blockIdx.x * 32 + nl] = tanhf(acc);
    }
}

// ---------------- persistent Kuramoto integrator + readout ----------------
extern __shared__ uint8_t dyn[];

__global__ void __launch_bounds__(THREADS, 1)
kuramoto_kernel(const float* __restrict__ omega,
                const float* __restrict__ init_phases,
                const float* __restrict__ kstr,
                const float* __restrict__ readout_w,
                float* __restrict__ out) {
    float* redS = (float*)(dyn + RED_OFF);          // [ (mt*8+ks)*16 + row16 ]
    float* redC = (float*)(dyn + RED_OFF + 1024);
    __shared__ float my_s[32], my_c[32], phi_sm[32], om_sm[32], ext_sm[32];
    __shared__ float sh_scale;

    const int tid  = threadIdx.x;
    const int bid  = blockIdx.x;
    const int lane = tid & 31;
    const int warp = tid >> 5;
    const int rowbase = bid * 32;

    // ---- prologue: copy this block's 128KB W fragment slice into smem ----
    {
        const uint4* src = (const uint4*)(g_Wf + (size_t)bid * W_BYTES_PER_BLOCK);
        uint4* dst = (uint4*)dyn;
        #pragma unroll
        for (int i = 0; i < 16; i++) dst[tid + i * THREADS] = __ldcg(src + tid + i * THREADS);
    }

    // ---- init: phases, omega, publish e4m3 sin/cos to buffer 0 ----
    if (tid == 0) sh_scale = kstr[0] * (1.0f / (float)N_OSC);
    if (tid < 32) {
        float p = init_phases[rowbase + tid];
        phi_sm[tid] = p;
        om_sm[tid]  = omega[rowbase + tid];
        float s, c;
        sincosf(p, &s, &c);
        my_s[tid] = s; my_c[tid] = c;
        unsigned short ps, pc;
        asm("cvt.rn.satfinite.e4m3x2.f32 %0, %1, %2;" : "=h"(ps) : "f"(0.0f), "f"(s));
        asm("cvt.rn.satfinite.e4m3x2.f32 %0, %1, %2;" : "=h"(pc) : "f"(0.0f), "f"(c));
        g_sc8[0][rowbase + tid]        = (uint8_t)ps;
        g_sc8[0][4096 + rowbase + tid] = (uint8_t)pc;
    }
    __syncthreads();
    if (tid == 0) { __threadfence(); atomicAdd(&g_arrive, 1u); }
    const float scale = sh_scale;

    const int mt = warp & 1;             // 16-row M tile
    const int ks = warp >> 1;            // k-slice: chunks [ks*16, ks*16+16)
    const uint8_t* Abase = dyn + (size_t)mt * 65536 + lane * 16;
    const uint8_t* bs = dyn + (((lane >> 2) & 1) ? SC_C_OFF : SC_S_OFF) + ((lane & 3) << 2);

    for (int sample = 0; sample < 4; sample++) {
        if (tid < 32) ext_sm[tid] = g_ext[sample][rowbase + tid];

        #pragma unroll 1
        for (int it = 0; it < 100; it++) {
            const int t = sample * 100 + it + 1;   // global step 1..400

            // ---- wait until all NB blocks published step t-1 ----
            if (tid == 0) {
                while (*(volatile unsigned*)&g_arrive < (unsigned)(t * NB)) { }
                __threadfence();   // acquire
            }
            __syncthreads();

            // ---- stage e4m3 (s, c) vectors (8KB) from L2 into smem ----
            {
                const uint8_t* gsrc = g_sc8[(t - 1) & 1];
                if (tid < 256)
                    *(uint4*)(dyn + SC_S_OFF + tid * 16) =
                        __ldcg((const uint4*)gsrc + tid);
                else
                    *(uint4*)(dyn + SC_C_OFF + (tid - 256) * 16) =
                        __ldcg((const uint4*)(gsrc + 4096) + (tid - 256));
            }
            __syncthreads();

            // ---- 16 rows x 512 cols per warp via 16x QMMA e4m3 ----
            float4 acc0 = {0.f, 0.f, 0.f, 0.f};
            float4 acc1 = {0.f, 0.f, 0.f, 0.f};
            #pragma unroll
            for (int i = 0; i < 16; i += 2) {
                int kc = ks * 16 + i;
                uint4 A0 = *(const uint4*)(Abase + (size_t)kc * 512);
                uint32_t b0 = *(const uint32_t*)(bs + kc * 32);
                uint32_t b1 = *(const uint32_t*)(bs + kc * 32 + 16);
                mma_e4m3(acc0, A0, b0, b1);
                uint4 A1 = *(const uint4*)(Abase + (size_t)(kc + 1) * 512);
                uint32_t b2 = *(const uint32_t*)(bs + (kc + 1) * 32);
                uint32_t b3 = *(const uint32_t*)(bs + (kc + 1) * 32 + 16);
                mma_e4m3(acc1, A1, b2, b3);
            }
            acc0.x += acc1.x; acc0.y += acc1.y; acc0.z += acc1.z; acc0.w += acc1.w;

            // lanes with lane%4==0 hold cols 0 (W@s) and 1 (W@c)
            if ((lane & 3) == 0) {
                int r = lane >> 2;
                int base = (mt * 8 + ks) * 16;
                redS[base + r]     = acc0.x;
                redC[base + r]     = acc0.y;
                redS[base + r + 8] = acc0.z;
                redC[base + r + 8] = acc0.w;
            }
            __syncthreads();

            // ---- phi update for this block's 32 rows (fp32) ----
            if (tid < 32) {
                int mtile = tid >> 4, r16 = tid & 15;
                float Ws = 0.f, Wc = 0.f;
                #pragma unroll
                for (int k = 0; k < 8; k++) {
                    Ws += redS[(mtile * 8 + k) * 16 + r16];
                    Wc += redC[(mtile * 8 + k) * 16 + r16];
                }
                float si = my_s[tid], ci = my_c[tid];
                float coup = ci * Ws - si * Wc;
                float p = phi_sm[tid] + DT_C * (om_sm[tid] + scale * coup + ext_sm[tid]);
                p = p - floorf(p * INV_TWO_PI_F) * TWO_PI_F;   // jnp.mod(p, 2pi)
                phi_sm[tid] = p;
                float s, c;
                __sincosf(p, &s, &c);
                my_s[tid] = s; my_c[tid] = c;
                unsigned short ps, pc;
                asm("cvt.rn.satfinite.e4m3x2.f32 %0, %1, %2;" : "=h"(ps) : "f"(0.0f), "f"(s));
                asm("cvt.rn.satfinite.e4m3x2.f32 %0, %1, %2;" : "=h"(pc) : "f"(0.0f), "f"(c));
                uint8_t* gb = g_sc8[t & 1];
                gb[rowbase + tid]        = (uint8_t)ps;
                gb[4096 + rowbase + tid] = (uint8_t)pc;
            }
            __syncthreads();
            if (tid == 0) { __threadfence(); atomicAdd(&g_arrive, 1u); }
        }

        // ---- readout: fold this block's 64 features into logits ----
        {
            float p0 = 0.f, p1 = 0.f;
            const int c0 = tid;
            const int c1 = tid + 512;
            const bool h1 = (c1 < 1000);
            #pragma unroll 1
            for (int j = 0; j < 32; j++) {
                float sj = my_s[j], cj = my_c[j];
                const float* rwS = readout_w + (size_t)(rowbase + j) * 1000;
                const float* rwC = readout_w + (size_t)(N_OSC + rowbase + j) * 1000;
                p0 += sj * rwS[c0] + cj * rwC[c0];
                if (h1) p1 += sj * rwS[c1] + cj * rwC[c1];
            }
            float* ob = out + sample * 1000;
            atomicAdd(ob + c0, p0);
            if (h1) atomicAdd(ob + c1, p1);
        }
    }
}

// ---------------- launch ----------------
extern "C" void kernel_launch(void* const* d_in, const int* in_sizes, int n_in,
                              void* d_out, int out_size) {
    const float* x     = (const float*)d_in[0];   // [4,2048]
    const float* enc_w = (const float*)d_in[1];   // [2048,4096]
    const float* enc_b = (const float*)d_in[2];   // [4096]
    const float* rw    = (const float*)d_in[3];   // [8192,1000]
    const float* rb    = (const float*)d_in[4];   // [1000]
    const float* omega = (const float*)d_in[5];   // [4096]
    const float* adjl  = (const float*)d_in[6];   // [4096,4096]
    const float* cplm  = (const float*)d_in[7];   // [4096,4096]
    const float* kstr  = (const float*)d_in[8];   // [1]
    const float* iphi  = (const float*)d_in[9];   // [4096]
    float* out = (float*)d_out;                   // [4,1000] fp32

    static bool attr_set = false;
    if (!attr_set) {
        cudaFuncSetAttribute(kuramoto_kernel,
                             cudaFuncAttributeMaxDynamicSharedMemorySize, DYN_SMEM);
        attr_set = true;
    }

    prep_kernel<<<16, 256>>>(out, rb);
    build_w_kernel<<<16384, 256>>>(adjl, cplm);
    relayout_kernel<<<4096, 256>>>();
    encoder_kernel<<<128, 256>>>(x, enc_w, enc_b);
    kuramoto_kernel<<<NB, THREADS, DYN_SMEM>>>(omega, iphi, kstr, rw, out);
}